// round 16
// baseline (speedup 1.0000x reference)
#include <cuda_runtime.h>
#include <cstdint>
#include <cstdio>

#define TSTEPS 4096
#define NTT    4095
#define VDIM   88
#define HDIM   512
#define RDIM   512
#define GS     20

// Gibbs work distribution: 120 consumer CTAs, 4 rows per batch, 9 rounds
#define GCTAS      120
#define ROUND_ROWS (GCTAS * 4)   // 480
#define NB         9

typedef unsigned long long ull;

// ---------------------------------------------------------------------------
// Scratch (static device globals — no runtime allocation allowed)
// ---------------------------------------------------------------------------
__device__ float    g_a    [NTT * RDIM];
__device__ float    g_uprev[NTT * RDIM];
__device__ float    g_bvt  [NTT * VDIM];
__device__ unsigned g_prog;
__device__ double   g_ce   [256];
__device__ double   g_n2uv [64];
__device__ double   g_n2uh [64];

// ---------------------------------------------------------------------------
// Helpers: packed fp32x2 ops (componentwise IEEE fp32 — order-preserving)
// ---------------------------------------------------------------------------
__device__ __forceinline__ ull fma2_(ull a, ull b, ull c) {
    ull d; asm("fma.rn.f32x2 %0, %1, %2, %3;" : "=l"(d) : "l"(a), "l"(b), "l"(c));
    return d;
}
__device__ __forceinline__ ull add2_(ull a, ull b) {
    ull d; asm("add.rn.f32x2 %0, %1, %2;" : "=l"(d) : "l"(a), "l"(b));
    return d;
}
__device__ __forceinline__ ull pack2_(float lo, float hi) {
    ull d; asm("mov.b64 %0, {%1, %2};" : "=l"(d) : "f"(lo), "f"(hi));
    return d;
}
__device__ __forceinline__ ull dup2_(float v) {
    ull d; asm("mov.b64 %0, {%1, %1};" : "=l"(d) : "f"(v));
    return d;
}
__device__ __forceinline__ float lo2_(ull v) { return __uint_as_float((unsigned)v); }
__device__ __forceinline__ float hi2_(ull v) { return __uint_as_float((unsigned)(v >> 32)); }

__device__ __forceinline__ void cluster_sync_() {
    asm volatile("barrier.cluster.arrive.aligned;\n\t"
                 "barrier.cluster.wait.aligned;" ::: "memory");
}
__device__ __forceinline__ uint32_t smem_u32(const void* p) {
    return (uint32_t)__cvta_generic_to_shared(p);
}

// ---------------------------------------------------------------------------
// NT GEMM (proven): C = A*B^T + bias. Used only for stage 1 (g_a).
// ---------------------------------------------------------------------------
template <int TM>
__global__ void __launch_bounds__(256, 2) gemm2_nt(
    const float* __restrict__ A, int lda,
    const float* __restrict__ B, int ldb,
    const float* __restrict__ bias,
    float* __restrict__ C, int ldc,
    int M, int N, int K)
{
    constexpr int BM  = 16 * TM;
    constexpr int KW  = TM;
    constexpr int TPR = 16 / KW;
    constexpr int AQ  = KW / 4;

    __shared__ __align__(16) float As[16][BM];
    __shared__ __align__(16) float Bs[16][64];

    const int tid = threadIdx.x;
    const int tx  = tid & 15;
    const int ty  = tid >> 4;
    const int m0  = blockIdx.x * BM;
    const int n0  = blockIdx.y * 64;

    const int arow  = tid / TPR;
    const int akb   = (tid % TPR) * KW;
    const int am    = m0 + arow;
    const bool amok = (am < M);
    const int brow  = tid >> 2;
    const int bkb   = (tid & 3) * 4;
    const int bn    = n0 + brow;
    const bool bnok = (bn < N);

    const float* Abase = A + (size_t)am * lda;
    const float* Bbase = B + (size_t)bn * ldb;
    const float4 z4 = make_float4(0.f, 0.f, 0.f, 0.f);

    float4 aR[AQ], bR;
#pragma unroll
    for (int q = 0; q < AQ; q++) {
        int k = akb + q * 4;
        aR[q] = (amok && k < K) ? *(const float4*)(Abase + k) : z4;
    }
    bR = (bnok && bkb < K) ? *(const float4*)(Bbase + bkb) : z4;

    ull acc[TM / 2][4];
#pragma unroll
    for (int i = 0; i < TM / 2; i++)
#pragma unroll
        for (int j = 0; j < 4; j++) acc[i][j] = 0ull;

    for (int k0 = 0; k0 < K; k0 += 16) {
#pragma unroll
        for (int q = 0; q < AQ; q++) {
            As[akb + q * 4 + 0][arow] = aR[q].x;
            As[akb + q * 4 + 1][arow] = aR[q].y;
            As[akb + q * 4 + 2][arow] = aR[q].z;
            As[akb + q * 4 + 3][arow] = aR[q].w;
        }
        Bs[bkb + 0][brow] = bR.x;
        Bs[bkb + 1][brow] = bR.y;
        Bs[bkb + 2][brow] = bR.z;
        Bs[bkb + 3][brow] = bR.w;
        __syncthreads();

        const int kn = k0 + 16;
        if (kn < K) {
#pragma unroll
            for (int q = 0; q < AQ; q++) {
                int k = kn + akb + q * 4;
                aR[q] = (amok && k < K) ? *(const float4*)(Abase + k) : z4;
            }
            int kb = kn + bkb;
            bR = (bnok && kb < K) ? *(const float4*)(Bbase + kb) : z4;
        }

#pragma unroll
        for (int k = 0; k < 16; k++) {
            float4 b4 = *(const float4*)&Bs[k][tx * 4];
            ull bb[4];
            bb[0] = dup2_(b4.x); bb[1] = dup2_(b4.y);
            bb[2] = dup2_(b4.z); bb[3] = dup2_(b4.w);
#pragma unroll
            for (int q = 0; q < TM / 4; q++) {
                ulonglong2 aa = *(const ulonglong2*)&As[k][ty * TM + q * 4];
#pragma unroll
                for (int c = 0; c < 4; c++) {
                    acc[2 * q + 0][c] = fma2_(aa.x, bb[c], acc[2 * q + 0][c]);
                    acc[2 * q + 1][c] = fma2_(aa.y, bb[c], acc[2 * q + 1][c]);
                }
            }
        }
        __syncthreads();
    }

#pragma unroll
    for (int i = 0; i < TM / 2; i++) {
#pragma unroll
        for (int half = 0; half < 2; half++) {
            const int m = m0 + ty * TM + 2 * i + half;
            if (m >= M) continue;
#pragma unroll
            for (int c = 0; c < 4; c++) {
                const int n = n0 + tx * 4 + c;
                if (n >= N) continue;
                float v = half ? hi2_(acc[i][c]) : lo2_(acc[i][c]);
                C[(size_t)m * ldc + n] = v + bias[n];
            }
        }
    }
}

// ---------------------------------------------------------------------------
// Fused kernel: cluster 0 (blocks 0..7) = sequential u recurrence (proven
// structure, unchanged math) + fenced progress publishes every 16 steps.
// Blocks 8..127 (15 clusters, never use cluster ops) = Gibbs consumers:
// wait for u rows, compute bh_t/bv_t with the identical ascending-k fmaf
// chain (bit-exact vs gemm2), then run the proven sparse 20-step Gibbs and
// write mse. Grid = 16 clusters of 8 -> all co-resident (1 CTA/SM).
// ---------------------------------------------------------------------------
#define WPITCH   89
#define W_FLOATS (512 * WPITCH + 96)
#define PAD_VOFF (88 * 4)
#define PAD_HOFF (512 * WPITCH * 4)
#define SMEM_BYTES 210688

__global__ void __cluster_dims__(8, 1, 1) __launch_bounds__(512, 1)
fused_kernel(const float* __restrict__ visible,
             const float* __restrict__ rand_h,
             const float* __restrict__ rand_v,
             const float* __restrict__ w,
             const float* __restrict__ wuu,
             const float* __restrict__ wuh,
             const float* __restrict__ wuv,
             const float* __restrict__ bh,
             const float* __restrict__ bv,
             const float* __restrict__ u0,
             const float* __restrict__ a,
             float* __restrict__ uprev,
             float* __restrict__ bvt_g,
             unsigned* __restrict__ prog,
             float* __restrict__ out)
{
    extern __shared__ __align__(16) char smraw[];
    const int tid  = threadIdx.x;
    const int wid  = tid >> 5;
    const int lane = tid & 31;

    if (blockIdx.x < 8) {
        // ================= recurrence role =================
        ull* u_d = (ull*)smraw;   // [2][RDIM] duplicated (u,u) pairs
        unsigned rank;
        asm("mov.u32 %0, %%cluster_ctarank;" : "=r"(rank));
        const int obase = (int)rank * 64 + wid * 4;

        ull w01[16], w23[16];
#pragma unroll
        for (int j = 0; j < 16; j++) {
            w01[j] = pack2_(wuu[(obase + 0) * RDIM + lane + 32 * j],
                            wuu[(obase + 1) * RDIM + lane + 32 * j]);
            w23[j] = pack2_(wuu[(obase + 2) * RDIM + lane + 32 * j],
                            wuu[(obase + 3) * RDIM + lane + 32 * j]);
        }
        {
            float ui = u0[tid];
            u_d[tid] = dup2_(ui);
            if (rank == 0) uprev[tid] = ui;
        }
        const uint32_t base0 = smem_u32(u_d);
        const uint32_t base1 = base0 + RDIM * 8u;

        cluster_sync_();

        int p = 0;
        for (int t = 0; t < NTT - 1; t++) {
            float av = 0.f;
            if (lane < 4) av = a[(size_t)t * RDIM + obase + lane];

            const ull* us = u_d + p * RDIM;
            ull s01 = 0ull, s23 = 0ull;
#pragma unroll
            for (int j = 0; j < 16; j++) {
                ull up = us[lane + 32 * j];
                s01 = fma2_(w01[j], up, s01);
                s23 = fma2_(w23[j], up, s23);
            }
#pragma unroll
            for (int off = 16; off; off >>= 1) {
                s01 = add2_(s01, __shfl_xor_sync(0xffffffffu, s01, off));
                s23 = add2_(s23, __shfl_xor_sync(0xffffffffu, s23, off));
            }
            if (lane < 4) {
                float acc = (lane == 0) ? lo2_(s01) : (lane == 1) ? hi2_(s01)
                          : (lane == 2) ? lo2_(s23) : hi2_(s23);
                float un = tanhf(acc + av);
                ull und = dup2_(un);
                uint32_t dst = (p ? base0 : base1) + 8u * (uint32_t)(obase + lane);
#pragma unroll
                for (unsigned r = 0; r < 8; r++) {
                    uint32_t rem;
                    asm volatile("mapa.shared::cluster.u32 %0, %1, %2;"
                                 : "=r"(rem) : "r"(dst), "r"(r));
                    asm volatile("st.shared::cluster.b64 [%0], %1;"
                                 :: "r"(rem), "l"(und) : "memory");
                }
                uprev[(size_t)(t + 1) * RDIM + obase + lane] = un;
            }
            if ((t & 15) == 15) __threadfence();   // make uprev visible gpu-wide
            cluster_sync_();
            if ((t & 15) == 15 && rank == 0 && tid == 0)
                *(volatile unsigned*)prog = (unsigned)(t + 2);
            p ^= 1;
        }
        __threadfence();
        cluster_sync_();
        if (rank == 0 && tid == 0) *(volatile unsigned*)prog = (unsigned)(NTT + 1);
        return;
    }

    // ==================== Gibbs role ====================
    const int cid = blockIdx.x - 8;   // 0..119

    float*    w_s       = (float*)smraw;                 // 45664
    float*    u_s4      = w_s + W_FLOATS;                // 4*512
    float*    bht_s     = u_s4 + 4 * 512;                // 4*512
    float*    bvt_s     = bht_s + 4 * 512;               // 4*88
    int*      h_list    = (int*)(bvt_s + 4 * 88);        // 4*520
    int*      v_list    = h_list + 4 * 520;              // 4*96
    unsigned* h_cnt     = (unsigned*)(v_list + 4 * 96);  // 4
    unsigned* v_cnt     = h_cnt + 4;                     // 4
    unsigned* vis_words = v_cnt + 4;                     // 12
    unsigned* v_words   = vis_words + 12;                // 12
    unsigned* h_words   = v_words + 12;                  // 64

    // Load w into smem (pitch 89); pad column + pad row zeroed.
    for (int idx = tid; idx < W_FLOATS; idx += 512) w_s[idx] = 0.f;
    __syncthreads();
    for (int idx = tid; idx < 512 * 88; idx += 512) {
        int j = idx / 88, i = idx - j * 88;
        w_s[j * WPITCH + i] = w[idx];
    }
    __syncthreads();

    for (int b = 0; b < NB; b++) {
        const int row0 = b * ROUND_ROWS + cid * 4;
        if (row0 >= NTT) break;
        const int lastrow = min(row0 + 3, NTT - 1);

        // ---- wait until recurrence has produced uprev rows <= lastrow ----
        if (tid == 0) {
            const unsigned need = (unsigned)(lastrow + 1);
            while (*(volatile unsigned*)prog < need) __nanosleep(256);
            __threadfence();   // acquire side
        }
        __syncthreads();

        // ---- load u rows into smem ----
        for (int idx = tid; idx < 4 * 512; idx += 512) {
            int r = idx >> 9, k = idx & 511;
            int row = row0 + r;
            u_s4[idx] = (row < NTT) ? uprev[(size_t)row * RDIM + k] : 0.f;
        }
        __syncthreads();

        // ---- bh_t rows: thread j, ascending-k chain (bit-exact vs gemm2) ----
        {
            const int j = tid;
            const float4* wr = (const float4*)(wuh + (size_t)j * RDIM);
            float a0 = 0.f, a1 = 0.f, a2 = 0.f, a3 = 0.f;
            for (int kq = 0; kq < 128; kq++) {
                float4 wv = wr[kq];
                float4 uA = *(const float4*)&u_s4[0 * 512 + kq * 4];
                float4 uB = *(const float4*)&u_s4[1 * 512 + kq * 4];
                float4 uC = *(const float4*)&u_s4[2 * 512 + kq * 4];
                float4 uD = *(const float4*)&u_s4[3 * 512 + kq * 4];
                a0 = fmaf(uA.x, wv.x, a0); a0 = fmaf(uA.y, wv.y, a0);
                a0 = fmaf(uA.z, wv.z, a0); a0 = fmaf(uA.w, wv.w, a0);
                a1 = fmaf(uB.x, wv.x, a1); a1 = fmaf(uB.y, wv.y, a1);
                a1 = fmaf(uB.z, wv.z, a1); a1 = fmaf(uB.w, wv.w, a1);
                a2 = fmaf(uC.x, wv.x, a2); a2 = fmaf(uC.y, wv.y, a2);
                a2 = fmaf(uC.z, wv.z, a2); a2 = fmaf(uC.w, wv.w, a2);
                a3 = fmaf(uD.x, wv.x, a3); a3 = fmaf(uD.y, wv.y, a3);
                a3 = fmaf(uD.z, wv.z, a3); a3 = fmaf(uD.w, wv.w, a3);
            }
            float bj = bh[j];
            bht_s[0 * 512 + j] = a0 + bj;
            bht_s[1 * 512 + j] = a1 + bj;
            bht_s[2 * 512 + j] = a2 + bj;
            bht_s[3 * 512 + j] = a3 + bj;
        }
        // ---- bv_t rows (threads < 352) ----
        if (tid < 352) {
            const int r = tid / 88, i = tid - r * 88;
            const int row = row0 + r;
            const float4* wr = (const float4*)(wuv + (size_t)i * RDIM);
            const float* ur = &u_s4[r * 512];
            float acc = 0.f;
            for (int kq = 0; kq < 128; kq++) {
                float4 wv = wr[kq];
                float4 uv = *(const float4*)&ur[kq * 4];
                acc = fmaf(uv.x, wv.x, acc); acc = fmaf(uv.y, wv.y, acc);
                acc = fmaf(uv.z, wv.z, acc); acc = fmaf(uv.w, wv.w, acc);
            }
            float val = acc + bv[i];
            bvt_s[r * 88 + i] = val;
            if (row < NTT) bvt_g[(size_t)row * VDIM + i] = val;
        }
        __syncthreads();

        // ---- init v bits + lists from visible (v_seq = visible[row+1]) ----
        if (wid < 4) {
            const int r = wid;
            const int row = row0 + r;
            const bool valid = (row < NTT);
            unsigned wds[3];
#pragma unroll
            for (int it = 0; it < 3; it++) {
                int i = it * 32 + lane;
                bool bit = valid && (i < VDIM) &&
                           (visible[(size_t)(row + 1) * VDIM + i] > 0.5f);
                wds[it] = __ballot_sync(0xffffffffu, bit);
            }
            if (lane < 3) { vis_words[r * 3 + lane] = wds[lane]; v_words[r * 3 + lane] = wds[lane]; }
            unsigned c = (lane < 3) ? __popc(wds[lane]) : 0;
            unsigned p0 = __shfl_sync(0xffffffffu, c, 0);
            unsigned p1 = __shfl_sync(0xffffffffu, c, 1);
            unsigned p2 = __shfl_sync(0xffffffffu, c, 2);
            unsigned total = p0 + p1 + p2;
            if (lane < 3) {
                unsigned pos = (lane == 0) ? 0 : (lane == 1) ? p0 : p0 + p1;
                unsigned x = wds[lane];
                while (x) {
                    int bb = __ffs(x) - 1;
                    v_list[r * 96 + pos++] = (lane * 32 + bb) * 4;
                    x &= x - 1;
                }
            }
            if (lane == 0) {
                unsigned t4 = (total + 3) & ~3u;
                for (unsigned q = total; q < t4; q++) v_list[r * 96 + q] = PAD_VOFF;
                v_cnt[r] = t4;
            }
        }
        __syncthreads();

        // ---- 20 Gibbs steps (proven sparse form) ----
        for (int s = 0; s < GS; s++) {
            // h-phase: thread j = tid
            {
                const int j = tid;
                float bh4[4], rh4[4], accs[4];
#pragma unroll
                for (int r = 0; r < 4; r++) {
                    const int row = row0 + r;
                    const bool valid = (row < NTT);
                    bh4[r] = bht_s[r * 512 + j];
                    rh4[r] = valid ? rand_h[((size_t)row * GS + s) * HDIM + j] : 2.f;
                }
                const char* wj = (const char*)(w_s + j * WPITCH);
#pragma unroll
                for (int r = 0; r < 4; r++) {
                    float acc = 0.f;
                    const int n = (int)v_cnt[r];
                    const int* lst = v_list + r * 96;
                    for (int m = 0; m < n; m += 4) {
                        int4 o = *(const int4*)(lst + m);
                        acc += *(const float*)(wj + o.x);
                        acc += *(const float*)(wj + o.y);
                        acc += *(const float*)(wj + o.z);
                        acc += *(const float*)(wj + o.w);
                    }
                    accs[r] = acc;
                }
#pragma unroll
                for (int r = 0; r < 4; r++) {
                    float pre = accs[r] + bh4[r];
                    float sg = 1.f / (1.f + expf(-pre));
                    bool bit = sg > rh4[r];
                    unsigned m = __ballot_sync(0xffffffffu, bit);
                    if (lane == 0) h_words[r * 16 + wid] = m;
                }
            }
            __syncthreads();

            // build h lists (warp r)
            if (wid < 4) {
                const int r = wid;
                unsigned wd = (lane < 16) ? h_words[r * 16 + lane] : 0u;
                unsigned c = __popc(wd);
                unsigned sc = c;
#pragma unroll
                for (int o = 1; o < 16; o <<= 1) {
                    unsigned v = __shfl_up_sync(0xffffffffu, sc, o);
                    if (lane >= o) sc += v;
                }
                unsigned total = __shfl_sync(0xffffffffu, sc, 15);
                if (lane < 16) {
                    unsigned pos = sc - c;
                    unsigned x = wd;
                    while (x) {
                        int bb = __ffs(x) - 1;
                        h_list[r * 520 + pos++] = (lane * 32 + bb) * (WPITCH * 4);
                        x &= x - 1;
                    }
                }
                if (lane == 0) {
                    unsigned t4 = (total + 3) & ~3u;
                    for (unsigned q = total; q < t4; q++) h_list[r * 520 + q] = PAD_HOFF;
                    h_cnt[r] = t4;
                }
            }
            __syncthreads();

            // v-phase: r = tid/96, i = tid%96
            {
                const int r = tid / 96;
                const int i = tid - r * 96;
                const bool inr = (r < 4);
                const int row = row0 + (inr ? r : 0);
                const bool act = inr && (i < VDIM) && (row < NTT);
                float bvv = (inr && i < VDIM) ? bvt_s[r * 88 + i] : 0.f;
                float rv = act ? rand_v[((size_t)row * GS + s) * VDIM + i] : 2.f;
                float acc = 0.f;
                if (inr) {
                    const int n = (int)h_cnt[r];
                    const int* lst = h_list + r * 520;
                    const char* wb = (const char*)w_s + i * 4;
                    for (int m = 0; m < n; m += 4) {
                        int4 o = *(const int4*)(lst + m);
                        acc += *(const float*)(wb + o.x);
                        acc += *(const float*)(wb + o.y);
                        acc += *(const float*)(wb + o.z);
                        acc += *(const float*)(wb + o.w);
                    }
                }
                float pre = acc + bvv;
                float sg = 1.f / (1.f + expf(-pre));
                bool bit = sg > rv;
                unsigned m = __ballot_sync(0xffffffffu, bit);
                if (lane == 0 && wid < 12) v_words[(wid / 3) * 3 + (wid % 3)] = m;
            }
            __syncthreads();

            // rebuild v lists (warp r)
            if (wid < 4) {
                const int r = wid;
                unsigned wd = (lane < 3) ? v_words[r * 3 + lane] : 0u;
                unsigned c = (lane < 3) ? __popc(wd) : 0;
                unsigned p0 = __shfl_sync(0xffffffffu, c, 0);
                unsigned p1 = __shfl_sync(0xffffffffu, c, 1);
                unsigned p2 = __shfl_sync(0xffffffffu, c, 2);
                unsigned total = p0 + p1 + p2;
                if (lane < 3) {
                    unsigned pos = (lane == 0) ? 0 : (lane == 1) ? p0 : p0 + p1;
                    unsigned x = wd;
                    while (x) {
                        int bb = __ffs(x) - 1;
                        v_list[r * 96 + pos++] = (lane * 32 + bb) * 4;
                        x &= x - 1;
                    }
                }
                if (lane == 0) {
                    unsigned t4 = (total + 3) & ~3u;
                    for (unsigned q = total; q < t4; q++) v_list[r * 96 + q] = PAD_VOFF;
                    v_cnt[r] = t4;
                }
            }
            __syncthreads();
        }

        // ---- mse: popcount(v ^ v_seq)/88 ----
        if (wid < 4) {
            const int r = wid, row = row0 + r;
            if (row < NTT) {
                unsigned d = (lane < 3) ? __popc(v_words[r * 3 + lane] ^ vis_words[r * 3 + lane]) : 0;
                d += __shfl_down_sync(0xffffffffu, d, 1);
                d += __shfl_down_sync(0xffffffffu, d, 2);
                if (lane == 0) out[1 + row] = (float)d / 88.0f;
            }
        }
        __syncthreads();
    }
}

// ---------------------------------------------------------------------------
// Small utility kernels
// ---------------------------------------------------------------------------
__global__ void reset_prog_kernel(unsigned* p) {
    if (threadIdx.x == 0) *p = 0u;
}

__global__ void ce_partial_kernel(const float* __restrict__ visible,
                                  const float* __restrict__ bvt, double* __restrict__ out) {
    __shared__ double sd[256];
    double s = 0.0;
    const int n = NTT * VDIM;
    for (int idx = blockIdx.x * 256 + threadIdx.x; idx < n; idx += gridDim.x * 256) {
        float x = bvt[idx];
        float y = 1.f / (1.f + expf(-x));
        float v = visible[idx + VDIM];
        float term = -(v * logf(1e-6f + y) + (1.f - v) * logf(1e-6f + 1.f - y));
        s += (double)term;
    }
    sd[threadIdx.x] = s;
    __syncthreads();
    for (int o = 128; o; o >>= 1) {
        if (threadIdx.x < o) sd[threadIdx.x] += sd[threadIdx.x + o];
        __syncthreads();
    }
    if (threadIdx.x == 0) out[blockIdx.x] = sd[0];
}

__global__ void sqsum_kernel(const float* __restrict__ x, int n, double* __restrict__ out) {
    __shared__ double sd[256];
    double s = 0.0;
    for (int i = blockIdx.x * 256 + threadIdx.x; i < n; i += gridDim.x * 256) {
        float f = x[i];
        s += (double)f * (double)f;
    }
    sd[threadIdx.x] = s;
    __syncthreads();
    for (int o = 128; o; o >>= 1) {
        if (threadIdx.x < o) sd[threadIdx.x] += sd[threadIdx.x + o];
        __syncthreads();
    }
    if (threadIdx.x == 0) out[blockIdx.x] = sd[0];
}

__global__ void finalize_kernel(const double* __restrict__ ce,
                                const double* __restrict__ n2uv,
                                const double* __restrict__ n2uh,
                                float* __restrict__ out) {
    __shared__ double s[256];
    const int t = threadIdx.x;
    s[t] = ce[t];
    __syncthreads();
    for (int o = 128; o; o >>= 1) { if (t < o) s[t] += s[t + o]; __syncthreads(); }
    double ce_sum = s[0];
    __syncthreads();
    s[t] = (t < 64) ? n2uv[t] : 0.0;
    __syncthreads();
    for (int o = 128; o; o >>= 1) { if (t < o) s[t] += s[t + o]; __syncthreads(); }
    double suv = s[0];
    __syncthreads();
    s[t] = (t < 64) ? n2uh[t] : 0.0;
    __syncthreads();
    for (int o = 128; o; o >>= 1) { if (t < o) s[t] += s[t + o]; __syncthreads(); }
    double suh = s[0];
    if (t == 0) {
        double reg = 0.2 * (sqrt(suv) + sqrt(suh));
        out[0]      = (float)(ce_sum / (double)TSTEPS + reg);
        out[TSTEPS] = (float)reg;
    }
}

// ---------------------------------------------------------------------------
// Launch
// ---------------------------------------------------------------------------
extern "C" void kernel_launch(void* const* d_in, const int* in_sizes, int n_in,
                              void* d_out, int out_size) {
    const float* visible = (const float*)d_in[0];
    const float* rand_h  = (const float*)d_in[1];
    const float* rand_v  = (const float*)d_in[2];
    const float* w       = (const float*)d_in[3];
    const float* wuu     = (const float*)d_in[4];
    const float* wuv     = (const float*)d_in[5];
    const float* wuh     = (const float*)d_in[6];
    const float* wvu     = (const float*)d_in[7];
    const float* bv      = (const float*)d_in[8];
    const float* bh      = (const float*)d_in[9];
    const float* bu      = (const float*)d_in[10];
    const float* u0      = (const float*)d_in[11];
    float* out = (float*)d_out;

    void *pa, *pu, *pbv, *pprog, *pce, *pnuv, *pnuh;
    cudaGetSymbolAddress(&pa,    g_a);
    cudaGetSymbolAddress(&pu,    g_uprev);
    cudaGetSymbolAddress(&pbv,   g_bvt);
    cudaGetSymbolAddress(&pprog, g_prog);
    cudaGetSymbolAddress(&pce,   g_ce);
    cudaGetSymbolAddress(&pnuv,  g_n2uv);
    cudaGetSymbolAddress(&pnuh,  g_n2uh);

    // 0) reset progress counter (every launch/replay)
    reset_prog_kernel<<<1, 32>>>((unsigned*)pprog);

    // 1) a[t] = v_seq[t] @ wvu^T + bu   (M=4095, N=512, K=88)
    {
        dim3 g((NTT + 127) / 128, (RDIM + 63) / 64);
        gemm2_nt<8><<<g, 256>>>(visible + VDIM, VDIM, wvu, VDIM,
                                bu, (float*)pa, RDIM, NTT, RDIM, VDIM);
    }

    // 2) fused recurrence + bh/bv + Gibbs + mse (single launch, 16 clusters)
    {
        cudaFuncSetAttribute(fused_kernel,
                             cudaFuncAttributeMaxDynamicSharedMemorySize, SMEM_BYTES);
        fused_kernel<<<8 + GCTAS, 512, SMEM_BYTES>>>(
            visible, rand_h, rand_v, w, wuu, wuh, wuv, bh, bv, u0,
            (const float*)pa, (float*)pu, (float*)pbv,
            (unsigned*)pprog, out);
    }

    // 3) reductions
    ce_partial_kernel<<<256, 256>>>(visible, (const float*)pbv, (double*)pce);
    sqsum_kernel<<<64, 256>>>(wuv, VDIM * RDIM, (double*)pnuv);
    sqsum_kernel<<<64, 256>>>(wuh, HDIM * RDIM, (double*)pnuh);
    finalize_kernel<<<1, 256>>>((const double*)pce, (const double*)pnuv,
                                (const double*)pnuh, out);
}